// round 15
// baseline (speedup 1.0000x reference)
#include <cuda_runtime.h>
#include <cuda_fp16.h>
#include <cstdint>

#define NB   8
#define CIN  64
#define COUT 128
#define HW   65536
#define HEADS 32

// ---------------- scratch (device globals; no allocation allowed) ----------
__device__ __align__(1024) uint4 g_zh4[(size_t)NB * HW * 16];      // conv out fp16 [n][s][c] (134MB)
__device__ __align__(1024) uint4 g_wh4[9216];                      // conv w fp16 [tap][co][ci]
__device__ __align__(1024) uint4 g_wkv4[1024];                     // proj w fp16 [kv][c]
__device__ float g_cps[NB * COUT * 512];
__device__ float g_cpss[NB * COUT * 512];
__device__ float g_mean[NB * COUT];
__device__ float g_inv[NB * COUT];
__device__ float g_kb2[NB * HEADS];
__device__ float g_vb2[NB * HEADS];
__device__ float g_pm[NB * HEADS * 512];
__device__ float g_pse[NB * HEADS * 512];
__device__ float g_psev[NB * HEADS * 512];
__device__ float g_ctx[NB * HEADS];
__device__ float g_bias[NB * COUT];

// ---------------- PTX helpers (baseline ISA: sm_80-level) -------------
__device__ __forceinline__ uint32_t smem_u32(const void* p) {
    uint32_t a;
    asm("{ .reg .u64 t; cvta.to.shared.u64 t, %1; cvt.u32.u64 %0, t; }" : "=r"(a) : "l"(p));
    return a;
}
__device__ __forceinline__ void ldsm4(uint32_t* r, uint32_t addr) {
    asm volatile("ldmatrix.sync.aligned.m8n8.x4.shared.b16 {%0,%1,%2,%3}, [%4];"
                 : "=r"(r[0]), "=r"(r[1]), "=r"(r[2]), "=r"(r[3]) : "r"(addr));
}
__device__ __forceinline__ void mma16816(float* c, const uint32_t* a, const uint32_t* b) {
    asm volatile(
        "mma.sync.aligned.m16n8k16.row.col.f32.f16.f16.f32 "
        "{%0,%1,%2,%3}, {%4,%5,%6,%7}, {%8,%9}, {%0,%1,%2,%3};"
        : "+f"(c[0]), "+f"(c[1]), "+f"(c[2]), "+f"(c[3])
        : "r"(a[0]), "r"(a[1]), "r"(a[2]), "r"(a[3]), "r"(b[0]), "r"(b[1]));
}

// =====================================================================
// Weight prep: conv + proj weights -> fp16
// =====================================================================
__global__ __launch_bounds__(256) void wprep_kernel(
    const float* __restrict__ cw, const float* __restrict__ kw,
    const float* __restrict__ vw)
{
    int e = blockIdx.x * 256 + threadIdx.x;
    if (e < 9 * 128 * 32) {
        int tap = e >> 12;
        int r = e & 4095;
        int co = r >> 5, cp = r & 31;
        int dy = tap / 3, dx = tap - dy * 3;
        uint32_t hp = 0;
#pragma unroll
        for (int j = 0; j < 2; j++) {
            int ci = 2 * cp + j;
            float wv = __ldg(cw + (((size_t)co * 64 + ci) * 3 + dy) * 3 + dx);
            hp |= (uint32_t)__half_as_ushort(__float2half(wv)) << (16 * j);
        }
        ((uint32_t*)g_wh4)[e] = hp;
    }
    if (e < 8192) {
        int kv = e >> 7, c = e & 127;
        int hh = kv >> 1;
        float val = (kv & 1) ? __ldg(vw + hh * 128 + c) : __ldg(kw + hh * 128 + c);
        ((uint16_t*)g_wkv4)[e] = __half_as_ushort(__float2half(val));
    }
}

// =====================================================================
// Conv via mma.sync, with the mixed=(x-y)+x*y prepass FUSED into the
// A-stage (computed under the HMMA shadow; no im2col buffer).
// CTA tile D[128px x 128co], 8 warps (4M x 2N), K = 3dy x 3dx x 64ci.
// Epilogue: +bias, PReLU -> fp16 z [s][c] + deterministic stats partials.
// =====================================================================
__global__ __launch_bounds__(256, 2) void conv_mma_kernel(
    const float* __restrict__ x, const float* __restrict__ yy,
    const float* __restrict__ cb, const float* __restrict__ pa_ptr)
{
    extern __shared__ __align__(16) char smem[];
    uint4* sm4 = (uint4*)smem;
    __half* s_ah = (__half*)smem;                  // AH[130 px][72 ci-stride]
    const uint32_t sbase = smem_u32(smem);

    const int tx = threadIdx.x;
    const int w = tx >> 5, lane = tx & 31;
    const int xh = blockIdx.x, yrow = blockIdx.y, n = blockIdx.z;
    const int x0 = xh * 128;
    const int wm = (w & 3) * 32;
    const int wn = (w >> 2) * 64;
    const int sub = lane >> 3, i8 = lane & 7;
    const int gid = lane >> 2, tig = lane & 3;

    // smem: AH[130][72] (18720B) @0 ; WH[3*128][72] (55296B) @18720 ; stats @74016
    const uint32_t AH = sbase;
    const uint32_t WHb = sbase + 18720;

    const uint32_t aA = ((i8 + ((sub & 1) << 3)) * 72 + ((sub >> 1) << 3)) * 2;
    const uint32_t aB = ((i8 + ((sub >> 1) << 3)) * 72 + ((sub & 1) << 3)) * 2;

    float acc[2][8][4];
#pragma unroll
    for (int fi = 0; fi < 2; fi++)
#pragma unroll
        for (int nf = 0; nf < 8; nf++)
#pragma unroll
            for (int r = 0; r < 4; r++) acc[fi][nf][r] = 0.f;

    const float* xb = x  + (size_t)n * CIN * HW;
    const float* yb = yy + (size_t)n * CIN * HW;

    for (int dy = 0; dy < 3; dy++) {
        int ys = yrow + dy - 1;
        if ((unsigned)ys > 255u) continue;
        {
            // fused prepass: compute mixed -> fp16 A tile directly
            const float* xrow = xb + (size_t)ys * 256;
            const float* yrow_ = yb + (size_t)ys * 256;
            for (int e = tx; e < 64 * 130; e += 256) {
                int ci = e / 130;
                int px = e - ci * 130;       // 0..129, gx = x0-1+px
                int gx = x0 - 1 + px;
                float m = 0.f;
                if ((unsigned)gx < 256u) {
                    size_t off = (size_t)ci * HW + gx;
                    float a = __ldg(xrow + off), b = __ldg(yrow_ + off);
                    m = (a - b) + a * b;
                }
                s_ah[px * 72 + ci] = __float2half(m);
            }
            // weights for this dy (3 dx taps)
            const size_t wb = (size_t)(3 * dy * 128) * 8;
            for (int e = tx; e < 3072; e += 256) {
                int r = e >> 3, c4 = e & 7;
                sm4[1170 + r * 9 + c4] = g_wh4[wb + (size_t)r * 8 + c4];
            }
        }
        __syncthreads();

#pragma unroll
        for (int dx = 0; dx < 3; dx++) {
#pragma unroll
            for (int kc = 0; kc < 4; kc++) {
                uint32_t Ah[2][4];
#pragma unroll
                for (int fi = 0; fi < 2; fi++) {
                    uint32_t off = (uint32_t)(((wm + fi * 16 + dx) * 72 + kc * 16) * 2);
                    ldsm4(Ah[fi], AH + aA + off);
                }
#pragma unroll
                for (int nf2 = 0; nf2 < 4; nf2++) {
                    uint32_t Bh[4];
                    uint32_t boff = (uint32_t)(((dx * 128 + wn + nf2 * 16) * 72 + kc * 16) * 2);
                    ldsm4(Bh, WHb + aB + boff);
#pragma unroll
                    for (int fi = 0; fi < 2; fi++) {
                        mma16816(acc[fi][2 * nf2],     Ah[fi], Bh);
                        mma16816(acc[fi][2 * nf2 + 1], Ah[fi], Bh + 2);
                    }
                }
            }
        }
        __syncthreads();
    }

    // ---- epilogue: +bias, PReLU, fp16 z to smem + stats partials ----
    float* s_st = (float*)(smem + 74016);          // [w][nf][tig][4]
    __half2* s_z = (__half2*)smem;                 // [128 px][64 co-pairs] 32KB
    const float pa = __ldg(pa_ptr);
#pragma unroll
    for (int nf = 0; nf < 8; nf++) {
        int co = wn + nf * 8 + 2 * tig;
        int cidx = (co >> 1);
        float b0 = __ldg(cb + co), b1 = __ldg(cb + co + 1);
        float S0 = 0.f, SS0 = 0.f, S1 = 0.f, SS1 = 0.f;
#pragma unroll
        for (int fi = 0; fi < 2; fi++) {
            int px = wm + fi * 16 + gid;
            float v0 = acc[fi][nf][0] + b0; v0 = (v0 >= 0.f) ? v0 : pa * v0;
            float v1 = acc[fi][nf][1] + b1; v1 = (v1 >= 0.f) ? v1 : pa * v1;
            float v2 = acc[fi][nf][2] + b0; v2 = (v2 >= 0.f) ? v2 : pa * v2;
            float v3 = acc[fi][nf][3] + b1; v3 = (v3 >= 0.f) ? v3 : pa * v3;
            s_z[px * 64 + cidx]       = __floats2half2_rn(v0, v1);
            s_z[(px + 8) * 64 + cidx] = __floats2half2_rn(v2, v3);
            S0 += v0 + v2; SS0 += v0 * v0 + v2 * v2;
            S1 += v1 + v3; SS1 += v1 * v1 + v3 * v3;
        }
#pragma unroll
        for (int o = 16; o >= 4; o >>= 1) {
            S0  += __shfl_down_sync(0xffffffffu, S0,  o);
            SS0 += __shfl_down_sync(0xffffffffu, SS0, o);
            S1  += __shfl_down_sync(0xffffffffu, S1,  o);
            SS1 += __shfl_down_sync(0xffffffffu, SS1, o);
        }
        if (lane < 4) {
            float* d = s_st + ((w * 8 + nf) * 4 + lane) * 4;
            d[0] = S0; d[1] = SS0; d[2] = S1; d[3] = SS1;
        }
    }
    __syncthreads();
    {
        int co = tx >> 1, which = tx & 1;
        int wg = co >> 6, nf = (co >> 3) & 7, tg = (co >> 1) & 3, j = co & 1;
        float sum = 0.f;
#pragma unroll
        for (int mw = 0; mw < 4; mw++)
            sum += s_st[(((wg * 4 + mw) * 8 + nf) * 4 + tg) * 4 + j * 2 + which];
        int slot = (n * COUT + co) * 512 + yrow * 2 + xh;
        if (which == 0) g_cps[slot] = sum; else g_cpss[slot] = sum;
    }
    // coalesced fp16 z store
    {
        const size_t zb = ((size_t)n * HW + (size_t)yrow * 256 + x0) * 16;
#pragma unroll
        for (int e = tx; e < 2048; e += 256)
            g_zh4[zb + e] = sm4[e];
    }
}

// =====================================================================
// Stats finalize
// =====================================================================
__global__ __launch_bounds__(256) void stats_kernel()
{
    const int nc = blockIdx.x;
    const int t = threadIdx.x;
    float S  = g_cps[nc * 512 + t]  + g_cps[nc * 512 + t + 256];
    float SS = g_cpss[nc * 512 + t] + g_cpss[nc * 512 + t + 256];
#pragma unroll
    for (int o = 16; o; o >>= 1) {
        S += __shfl_down_sync(0xffffffffu, S, o);
        SS += __shfl_down_sync(0xffffffffu, SS, o);
    }
    __shared__ float sS[8], sSS[8];
    if ((t & 31) == 0) { sS[t >> 5] = S; sSS[t >> 5] = SS; }
    __syncthreads();
    if (t == 0) {
        S = 0.f; SS = 0.f;
#pragma unroll
        for (int w = 0; w < 8; w++) { S += sS[w]; SS += sSS[w]; }
        float mean = S * (1.f / 65536.f);
        float var = SS * (1.f / 65536.f) - mean * mean;
        g_mean[nc] = mean;
        g_inv[nc] = rsqrtf(var + 1e-5f);
    }
}

// =====================================================================
// kb2: effective projection biases (norm folded)
// =====================================================================
__global__ void kb2_kernel(const float* __restrict__ kw, const float* __restrict__ kb,
                           const float* __restrict__ vw, const float* __restrict__ vb)
{
    int t = threadIdx.x;           // 256 = 8n x 32h
    int n = t >> 5, h = t & 31;
    float k2 = __ldg(kb + h), v2 = __ldg(vb + h);
    for (int c = 0; c < 128; c++) {
        float mi = g_mean[n * 128 + c] * g_inv[n * 128 + c];
        k2 -= __ldg(kw + h * 128 + c) * mi;
        v2 -= __ldg(vw + h * 128 + c) * mi;
    }
    g_kb2[t] = k2;
    g_vb2[t] = v2;
}

// =====================================================================
// Proj via fp16 mma.sync: D[128s x 64kv], K=128; register softmax partials.
// =====================================================================
__global__ __launch_bounds__(256) void proj_kernel()
{
    extern __shared__ __align__(16) char psm[];
    const uint32_t sbase = smem_u32(psm);
    uint4* sm4 = (uint4*)psm;
    __half* s_invh = (__half*)(psm + 52224);
    float* s_kb = (float*)(psm + 52480);
    float* s_pm = (float*)(psm + 52736);          // [8w][32h]
    float* s_pse = s_pm + 256;
    float* s_psev = s_pse + 256;

    const int n = blockIdx.y, bx = blockIdx.x;
    const int t = threadIdx.x;
    const int w = t >> 5, lane = t & 31;
    const int sub = lane >> 3, i8 = lane & 7;
    const int gid = lane >> 2, tig = lane & 3;

    if (t < 128) s_invh[t] = __float2half(g_inv[n * 128 + t]);
    if (t >= 128 && t < 160) s_kb[t - 128] = g_kb2[n * 32 + (t - 128)];
    if (t >= 160 && t < 192) s_kb[t - 128] = g_vb2[n * 32 + (t - 160)];
    __syncthreads();

    {
        const size_t zb = ((size_t)n * HW + (size_t)bx * 128) * 16;
        for (int e = t; e < 2048; e += 256) {
            int r = e >> 4, u = e & 15;
            uint4 q = g_zh4[zb + e];
            __half2* qq = (__half2*)&q;
            const __half2* iv = (const __half2*)&s_invh[u * 8];
#pragma unroll
            for (int j = 0; j < 4; j++) qq[j] = __hmul2(qq[j], iv[j]);
            sm4[r * 17 + u] = q;
        }
        for (int e = t; e < 1024; e += 256) {
            int r = e >> 4, u = e & 15;
            sm4[2176 + r * 17 + u] = g_wkv4[e];
        }
    }
    __syncthreads();

    const uint32_t AB = sbase;
    const uint32_t WB = sbase + 34816;
    const uint32_t aA = ((i8 + ((sub & 1) << 3)) * 136 + ((sub >> 1) << 3)) * 2;
    const uint32_t aB = ((i8 + ((sub >> 1) << 3)) * 136 + ((sub & 1) << 3)) * 2;

    float acc[4][2][4];
#pragma unroll
    for (int a = 0; a < 4; a++)
#pragma unroll
        for (int b = 0; b < 2; b++)
#pragma unroll
            for (int r = 0; r < 4; r++) acc[a][b][r] = 0.f;

#pragma unroll
    for (int kc = 0; kc < 8; kc++) {
        uint32_t Af[4];
        ldsm4(Af, AB + aA + (uint32_t)((w * 16 * 136 + kc * 16) * 2));
#pragma unroll
        for (int nf2 = 0; nf2 < 4; nf2++) {
            uint32_t Bf[4];
            ldsm4(Bf, WB + aB + (uint32_t)(((nf2 * 16) * 136 + kc * 16) * 2));
            mma16816(acc[nf2][0], Af, Bf);
            mma16816(acc[nf2][1], Af, Bf + 2);
        }
    }

#pragma unroll
    for (int nf2 = 0; nf2 < 4; nf2++) {
#pragma unroll
        for (int half = 0; half < 2; half++) {
            int h = nf2 * 8 + half * 4 + tig;
            float kb2v = s_kb[h], vb2v = s_kb[32 + h];
            float k1 = acc[nf2][half][0] + kb2v;
            float v1 = acc[nf2][half][1] + vb2v;
            float k2 = acc[nf2][half][2] + kb2v;
            float v2 = acc[nf2][half][3] + vb2v;
            float m = fmaxf(k1, k2);
#pragma unroll
            for (int o = 4; o <= 16; o <<= 1)
                m = fmaxf(m, __shfl_xor_sync(0xffffffffu, m, o));
            float e1 = expf(k1 - m), e2 = expf(k2 - m);
            float se = e1 + e2, sev = e1 * v1 + e2 * v2;
#pragma unroll
            for (int o = 4; o <= 16; o <<= 1) {
                se += __shfl_xor_sync(0xffffffffu, se, o);
                sev += __shfl_xor_sync(0xffffffffu, sev, o);
            }
            if (gid == 0) {
                s_pm[w * 32 + h] = m;
                s_pse[w * 32 + h] = se;
                s_psev[w * 32 + h] = sev;
            }
        }
    }
    __syncthreads();

    if (t < 32) {
        int h = t;
        float m = s_pm[h];
#pragma unroll
        for (int ww = 1; ww < 8; ww++) m = fmaxf(m, s_pm[ww * 32 + h]);
        float se = 0.f, sev = 0.f;
#pragma unroll
        for (int ww = 0; ww < 8; ww++) {
            float sc = expf(s_pm[ww * 32 + h] - m);
            se += s_pse[ww * 32 + h] * sc;
            sev += s_psev[ww * 32 + h] * sc;
        }
        int idx = (n * 32 + h) * 512 + bx;
        g_pm[idx] = m;
        g_pse[idx] = se;
        g_psev[idx] = sev;
    }
}

// =====================================================================
// Merge softmax partials (512 per head) -> context[n,h]
// =====================================================================
__global__ void ctx_kernel()
{
    const int nh = blockIdx.x;
    const int t = threadIdx.x;      // 128
    const int base = nh * 512;
    const int lane = t & 31, wrp = t >> 5;
    __shared__ float sred[4];
    __shared__ float sM;

    float lm[4];
    float m = -1e30f;
#pragma unroll
    for (int i = 0; i < 4; i++) {
        lm[i] = g_pm[base + t + 128 * i];
        m = fmaxf(m, lm[i]);
    }
#pragma unroll
    for (int o = 16; o; o >>= 1) m = fmaxf(m, __shfl_xor_sync(0xffffffffu, m, o));
    if (lane == 0) sred[wrp] = m;
    __syncthreads();
    if (t == 0) sM = fmaxf(fmaxf(sred[0], sred[1]), fmaxf(sred[2], sred[3]));
    __syncthreads();
    const float M = sM;

    float S = 0.f, SV = 0.f;
#pragma unroll
    for (int i = 0; i < 4; i++) {
        int idx = base + t + 128 * i;
        float sc = expf(lm[i] - M);
        S += g_pse[idx] * sc;
        SV += g_psev[idx] * sc;
    }
#pragma unroll
    for (int o = 16; o; o >>= 1) {
        S += __shfl_xor_sync(0xffffffffu, S, o);
        SV += __shfl_xor_sync(0xffffffffu, SV, o);
    }
    __shared__ float sS[4], sSV[4];
    if (lane == 0) { sS[wrp] = S; sSV[wrp] = SV; }
    __syncthreads();
    if (t == 0) {
        S = sS[0] + sS[1] + sS[2] + sS[3];
        SV = sSV[0] + sSV[1] + sSV[2] + sSV[3];
        g_ctx[nh] = SV / S;
    }
}

__global__ void biasout_kernel(const float* __restrict__ rw, const float* __restrict__ rb)
{
    int n = blockIdx.x;
    int c = threadIdx.x;   // 128
    float b = __ldg(rb + c);
#pragma unroll
    for (int h = 0; h < 32; h++)
        b += __ldg(rw + c * 32 + h) * g_ctx[n * 32 + h];
    g_bias[n * 128 + c] = b;
}

// =====================================================================
// Out: read fp16 z [s][c], transpose via smem, write NCHW fp32
//      out = z*inv + (bias - mean*inv)
// =====================================================================
__global__ __launch_bounds__(256) void out_kernel(float* __restrict__ out)
{
    extern __shared__ float osm[];          // [128 s][133 c-pad] + inv/off
    float* s_inv = osm + 17024;
    float* s_off = s_inv + 128;

    const int n = blockIdx.y, bx = blockIdx.x;
    const int t = threadIdx.x;
    const int w = t >> 5, lane = t & 31;

    if (t < 128) {
        float iv = g_inv[n * 128 + t];
        s_inv[t] = iv;
        s_off[t] = g_bias[n * 128 + t] - g_mean[n * 128 + t] * iv;
    }

    const size_t zb = ((size_t)n * HW + (size_t)bx * 128) * 16;
    for (int e = t; e < 2048; e += 256) {
        int r = e >> 4, u = e & 15;
        uint4 q = g_zh4[zb + e];
        const __half2* qq = (const __half2*)&q;
        float* d = osm + r * 133 + u * 8;
#pragma unroll
        for (int j = 0; j < 4; j++) {
            float2 f = __half22float2(qq[j]);
            d[2 * j] = f.x; d[2 * j + 1] = f.y;
        }
    }
    __syncthreads();

#pragma unroll
    for (int ci = 0; ci < 16; ci++) {
        int c = w * 16 + ci;
        float iv = s_inv[c], off = s_off[c];
        size_t ob = (size_t)(n * COUT + c) * HW + (size_t)bx * 128;
#pragma unroll
        for (int j = 0; j < 4; j++) {
            int s = lane + 32 * j;
            out[ob + s] = fmaf(osm[s * 133 + c], iv, off);
        }
    }
}

extern "C" void kernel_launch(void* const* d_in, const int* in_sizes, int n_in,
                              void* d_out, int out_size)
{
    const float* x  = (const float*)d_in[0];
    const float* y  = (const float*)d_in[1];
    const float* cw = (const float*)d_in[2];
    const float* cb = (const float*)d_in[3];
    const float* pa = (const float*)d_in[4];
    const float* kw = (const float*)d_in[5];
    const float* kb = (const float*)d_in[6];
    // d_in[7], d_in[8] = queries_w/b: mathematically dead (softmax over size-1 axis)
    const float* vw = (const float*)d_in[9];
    const float* vb = (const float*)d_in[10];
    const float* rw = (const float*)d_in[11];
    const float* rb = (const float*)d_in[12];

    static bool attr_set = false;
    if (!attr_set) {
        cudaFuncSetAttribute(conv_mma_kernel,
                             cudaFuncAttributeMaxDynamicSharedMemorySize, 78112);
        cudaFuncSetAttribute(proj_kernel,
                             cudaFuncAttributeMaxDynamicSharedMemorySize, 56064);
        cudaFuncSetAttribute(out_kernel,
                             cudaFuncAttributeMaxDynamicSharedMemorySize, 69632);
        attr_set = true;
    }

    wprep_kernel<<<144, 256>>>(cw, kw, vw);
    conv_mma_kernel<<<dim3(2, 256, 8), 256, 78112>>>(x, y, cb, pa);
    stats_kernel<<<1024, 256>>>();
    kb2_kernel<<<1, 256>>>(kw, kb, vw, vb);
    proj_kernel<<<dim3(512, 8), 256, 56064>>>();
    ctx_kernel<<<256, 128>>>();
    biasout_kernel<<<8, 128>>>(rw, rb);
    out_kernel<<<dim3(512, 8), 256, 69632>>>((float*)d_out);
}

// round 16
// speedup vs baseline: 1.0779x; 1.0779x over previous
#include <cuda_runtime.h>
#include <cuda_fp16.h>
#include <cstdint>

#define NB   8
#define CIN  64
#define COUT 128
#define HW   65536
#define HEADS 32

// ---------------- scratch (device globals; no allocation allowed) ----------
__device__ __align__(1024) uint4 g_zh4[(size_t)NB * HW * 16];      // conv out fp16 [n][s][c] (134MB)
__device__ __align__(1024) uint4 g_imh4[(size_t)2048 * 258 * 9];   // im2col fp16 rows
__device__ __align__(1024) uint4 g_wh4[9216];                      // conv w fp16 [tap][co][ci]
__device__ __align__(1024) uint4 g_wkv4[1024];                     // proj w fp16 [kv][c]
__device__ float g_cps[NB * COUT * 512];
__device__ float g_cpss[NB * COUT * 512];
__device__ float g_mean[NB * COUT];
__device__ float g_inv[NB * COUT];
__device__ float g_kb2[NB * HEADS];
__device__ float g_vb2[NB * HEADS];
__device__ float g_pm[NB * HEADS * 512];
__device__ float g_pse[NB * HEADS * 512];
__device__ float g_psev[NB * HEADS * 512];
__device__ float g_ctx[NB * HEADS];
__device__ float g_bias[NB * COUT];

// ---------------- PTX helpers (baseline ISA: sm_80-level) -------------
__device__ __forceinline__ uint32_t smem_u32(const void* p) {
    uint32_t a;
    asm("{ .reg .u64 t; cvta.to.shared.u64 t, %1; cvt.u32.u64 %0, t; }" : "=r"(a) : "l"(p));
    return a;
}
__device__ __forceinline__ void ldsm4(uint32_t* r, uint32_t addr) {
    asm volatile("ldmatrix.sync.aligned.m8n8.x4.shared.b16 {%0,%1,%2,%3}, [%4];"
                 : "=r"(r[0]), "=r"(r[1]), "=r"(r[2]), "=r"(r[3]) : "r"(addr));
}
__device__ __forceinline__ void mma16816(float* c, const uint32_t* a, const uint32_t* b) {
    asm volatile(
        "mma.sync.aligned.m16n8k16.row.col.f32.f16.f16.f32 "
        "{%0,%1,%2,%3}, {%4,%5,%6,%7}, {%8,%9}, {%0,%1,%2,%3};"
        : "+f"(c[0]), "+f"(c[1]), "+f"(c[2]), "+f"(c[3])
        : "r"(a[0]), "r"(a[1]), "r"(a[2]), "r"(a[3]), "r"(b[0]), "r"(b[1]));
}

// =====================================================================
// Prepass: mixed=(x-y)+x*y -> fp16 rows with 1px halo each side.
// (smem-staged, coalesced stores — proven)
// =====================================================================
__global__ __launch_bounds__(256) void prepass_kernel(
    const float* __restrict__ x, const float* __restrict__ yy)
{
    __shared__ uint32_t m_h[130][68];    // half bits in low 16

    const int xh = blockIdx.x, yrow = blockIdx.y, n = blockIdx.z;
    const int x0 = xh * 128;
    const int tx = threadIdx.x;

    const float* xb = x  + (size_t)n * CIN * HW + (size_t)yrow * 256;
    const float* yb = yy + (size_t)n * CIN * HW + (size_t)yrow * 256;

    for (int e = tx; e < 64 * 34; e += 256) {
        int ci = e / 34, q = e - ci * 34;
        int gx = x0 - 4 + q * 4;
        float4 xv = make_float4(0.f, 0.f, 0.f, 0.f), yv = xv;
        if (gx >= 0 && gx + 3 < 256) {
            xv = *(const float4*)(xb + (size_t)ci * HW + gx);
            yv = *(const float4*)(yb + (size_t)ci * HW + gx);
        } else {
#pragma unroll
            for (int j = 0; j < 4; j++) {
                int g = gx + j;
                if ((unsigned)g < 256u) {
                    ((float*)&xv)[j] = xb[(size_t)ci * HW + g];
                    ((float*)&yv)[j] = yb[(size_t)ci * HW + g];
                }
            }
        }
#pragma unroll
        for (int j = 0; j < 4; j++) {
            int g = gx + j;
            int lp = g - x0 + 1;
            if ((unsigned)lp > 129u) continue;
            float m = 0.f;
            if ((unsigned)g < 256u) {
                float a = ((float*)&xv)[j], b = ((float*)&yv)[j];
                m = (a - b) + a * b;
            }
            m_h[lp][ci] = (uint32_t)__half_as_ushort(__float2half(m));
        }
    }
    __syncthreads();

    uint32_t* oh = (uint32_t*)g_imh4;
    const size_t rbase = ((size_t)(n * 256 + yrow) * 258 + x0) * 36;
    for (int e = tx; e < 130 * 32; e += 256) {
        int lp = e >> 5, cp = e & 31;
        uint32_t w0 = m_h[lp][2 * cp], w1 = m_h[lp][2 * cp + 1];
        oh[rbase + (size_t)lp * 36 + cp] = __byte_perm(w0, w1, 0x5410);
    }
}

// =====================================================================
// Weight prep: conv + proj weights -> fp16
// =====================================================================
__global__ __launch_bounds__(256) void wprep_kernel(
    const float* __restrict__ cw, const float* __restrict__ kw,
    const float* __restrict__ vw)
{
    int e = blockIdx.x * 256 + threadIdx.x;
    if (e < 9 * 128 * 32) {
        int tap = e >> 12;
        int r = e & 4095;
        int co = r >> 5, cp = r & 31;
        int dy = tap / 3, dx = tap - dy * 3;
        uint32_t hp = 0;
#pragma unroll
        for (int j = 0; j < 2; j++) {
            int ci = 2 * cp + j;
            float wv = __ldg(cw + (((size_t)co * 64 + ci) * 3 + dy) * 3 + dx);
            hp |= (uint32_t)__half_as_ushort(__float2half(wv)) << (16 * j);
        }
        ((uint32_t*)g_wh4)[e] = hp;
    }
    if (e < 8192) {
        int kv = e >> 7, c = e & 127;
        int hh = kv >> 1;
        float val = (kv & 1) ? __ldg(vw + hh * 128 + c) : __ldg(kw + hh * 128 + c);
        ((uint16_t*)g_wkv4)[e] = __half_as_ushort(__float2half(val));
    }
}

// =====================================================================
// Conv via mma.sync (HMMA f16): single fp16 A x single fp16 B.
// CTA tile D[128px x 128co], 8 warps (4M x 2N), K = 3dy x 3dx x 64ci.
// Epilogue: +bias, PReLU -> fp16 z [s][c] + deterministic stats partials.
// =====================================================================
__global__ __launch_bounds__(256, 2) void conv_mma_kernel(
    const float* __restrict__ cb, const float* __restrict__ pa_ptr)
{
    extern __shared__ __align__(16) char smem[];
    uint4* sm4 = (uint4*)smem;
    const uint32_t sbase = smem_u32(smem);

    const int tx = threadIdx.x;
    const int w = tx >> 5, lane = tx & 31;
    const int xh = blockIdx.x, yrow = blockIdx.y, n = blockIdx.z;
    const int x0 = xh * 128;
    const int wm = (w & 3) * 32;
    const int wn = (w >> 2) * 64;
    const int sub = lane >> 3, i8 = lane & 7;
    const int gid = lane >> 2, tig = lane & 3;

    // smem: AH[130][72] (18720B) @0 ; WH[3*128][72] (55296B) @18720 ; stats @74016
    const uint32_t AH = sbase;
    const uint32_t WHb = sbase + 18720;

    const uint32_t aA = ((i8 + ((sub & 1) << 3)) * 72 + ((sub >> 1) << 3)) * 2;
    const uint32_t aB = ((i8 + ((sub >> 1) << 3)) * 72 + ((sub & 1) << 3)) * 2;

    float acc[2][8][4];
#pragma unroll
    for (int fi = 0; fi < 2; fi++)
#pragma unroll
        for (int nf = 0; nf < 8; nf++)
#pragma unroll
            for (int r = 0; r < 4; r++) acc[fi][nf][r] = 0.f;

    for (int dy = 0; dy < 3; dy++) {
        int ys = yrow + dy - 1;
        if ((unsigned)ys > 255u) continue;
        {
            const size_t rb = ((size_t)(n * 256 + ys) * 258 + x0) * 9;
            for (int e = tx; e < 1040; e += 256) {
                int la = e >> 3, c4 = e & 7;
                sm4[la * 9 + c4] = g_imh4[rb + (size_t)la * 9 + c4];
            }
            const size_t wb = (size_t)(3 * dy * 128) * 8;
            for (int e = tx; e < 3072; e += 256) {
                int r = e >> 3, c4 = e & 7;
                sm4[1170 + r * 9 + c4] = g_wh4[wb + (size_t)r * 8 + c4];
            }
        }
        __syncthreads();

#pragma unroll
        for (int dx = 0; dx < 3; dx++) {
#pragma unroll
            for (int kc = 0; kc < 4; kc++) {
                uint32_t Ah[2][4];
#pragma unroll
                for (int fi = 0; fi < 2; fi++) {
                    uint32_t off = (uint32_t)(((wm + fi * 16 + dx) * 72 + kc * 16) * 2);
                    ldsm4(Ah[fi], AH + aA + off);
                }
#pragma unroll
                for (int nf2 = 0; nf2 < 4; nf2++) {
                    uint32_t Bh[4];
                    uint32_t boff = (uint32_t)(((dx * 128 + wn + nf2 * 16) * 72 + kc * 16) * 2);
                    ldsm4(Bh, WHb + aB + boff);
#pragma unroll
                    for (int fi = 0; fi < 2; fi++) {
                        mma16816(acc[fi][2 * nf2],     Ah[fi], Bh);
                        mma16816(acc[fi][2 * nf2 + 1], Ah[fi], Bh + 2);
                    }
                }
            }
        }
        __syncthreads();
    }

    // ---- epilogue: +bias, PReLU, fp16 z to smem + stats partials ----
    float* s_st = (float*)(smem + 74016);          // [w][nf][tig][4]
    __half2* s_z = (__half2*)smem;                 // [128 px][64 co-pairs] 32KB
    const float pa = __ldg(pa_ptr);
#pragma unroll
    for (int nf = 0; nf < 8; nf++) {
        int co = wn + nf * 8 + 2 * tig;
        int cidx = (co >> 1);
        float b0 = __ldg(cb + co), b1 = __ldg(cb + co + 1);
        float S0 = 0.f, SS0 = 0.f, S1 = 0.f, SS1 = 0.f;
#pragma unroll
        for (int fi = 0; fi < 2; fi++) {
            int px = wm + fi * 16 + gid;
            float v0 = acc[fi][nf][0] + b0; v0 = (v0 >= 0.f) ? v0 : pa * v0;
            float v1 = acc[fi][nf][1] + b1; v1 = (v1 >= 0.f) ? v1 : pa * v1;
            float v2 = acc[fi][nf][2] + b0; v2 = (v2 >= 0.f) ? v2 : pa * v2;
            float v3 = acc[fi][nf][3] + b1; v3 = (v3 >= 0.f) ? v3 : pa * v3;
            s_z[px * 64 + cidx]       = __floats2half2_rn(v0, v1);
            s_z[(px + 8) * 64 + cidx] = __floats2half2_rn(v2, v3);
            S0 += v0 + v2; SS0 += v0 * v0 + v2 * v2;
            S1 += v1 + v3; SS1 += v1 * v1 + v3 * v3;
        }
#pragma unroll
        for (int o = 16; o >= 4; o >>= 1) {
            S0  += __shfl_down_sync(0xffffffffu, S0,  o);
            SS0 += __shfl_down_sync(0xffffffffu, SS0, o);
            S1  += __shfl_down_sync(0xffffffffu, S1,  o);
            SS1 += __shfl_down_sync(0xffffffffu, SS1, o);
        }
        if (lane < 4) {
            float* d = s_st + ((w * 8 + nf) * 4 + lane) * 4;
            d[0] = S0; d[1] = SS0; d[2] = S1; d[3] = SS1;
        }
    }
    __syncthreads();
    {
        int co = tx >> 1, which = tx & 1;
        int wg = co >> 6, nf = (co >> 3) & 7, tg = (co >> 1) & 3, j = co & 1;
        float sum = 0.f;
#pragma unroll
        for (int mw = 0; mw < 4; mw++)
            sum += s_st[(((wg * 4 + mw) * 8 + nf) * 4 + tg) * 4 + j * 2 + which];
        int slot = (n * COUT + co) * 512 + yrow * 2 + xh;
        if (which == 0) g_cps[slot] = sum; else g_cpss[slot] = sum;
    }
    // coalesced fp16 z store
    {
        const size_t zb = ((size_t)n * HW + (size_t)yrow * 256 + x0) * 16;
#pragma unroll
        for (int e = tx; e < 2048; e += 256)
            g_zh4[zb + e] = sm4[e];
    }
}

// =====================================================================
// Stats finalize
// =====================================================================
__global__ __launch_bounds__(256) void stats_kernel()
{
    const int nc = blockIdx.x;
    const int t = threadIdx.x;
    float S  = g_cps[nc * 512 + t]  + g_cps[nc * 512 + t + 256];
    float SS = g_cpss[nc * 512 + t] + g_cpss[nc * 512 + t + 256];
#pragma unroll
    for (int o = 16; o; o >>= 1) {
        S += __shfl_down_sync(0xffffffffu, S, o);
        SS += __shfl_down_sync(0xffffffffu, SS, o);
    }
    __shared__ float sS[8], sSS[8];
    if ((t & 31) == 0) { sS[t >> 5] = S; sSS[t >> 5] = SS; }
    __syncthreads();
    if (t == 0) {
        S = 0.f; SS = 0.f;
#pragma unroll
        for (int w = 0; w < 8; w++) { S += sS[w]; SS += sSS[w]; }
        float mean = S * (1.f / 65536.f);
        float var = SS * (1.f / 65536.f) - mean * mean;
        g_mean[nc] = mean;
        g_inv[nc] = rsqrtf(var + 1e-5f);
    }
}

// =====================================================================
// kb2 (PARALLEL): one block per (head, batch); 128 threads reduce over c.
// =====================================================================
__global__ __launch_bounds__(128) void kb2_kernel(
    const float* __restrict__ kw, const float* __restrict__ kb,
    const float* __restrict__ vw, const float* __restrict__ vb)
{
    const int h = blockIdx.x, n = blockIdx.y;
    const int c = threadIdx.x;                   // 0..127
    const int lane = c & 31, wrp = c >> 5;

    float mi = g_mean[n * 128 + c] * g_inv[n * 128 + c];
    float kk = __ldg(kw + h * 128 + c) * mi;
    float vv = __ldg(vw + h * 128 + c) * mi;
#pragma unroll
    for (int o = 16; o; o >>= 1) {
        kk += __shfl_down_sync(0xffffffffu, kk, o);
        vv += __shfl_down_sync(0xffffffffu, vv, o);
    }
    __shared__ float sK[4], sV[4];
    if (lane == 0) { sK[wrp] = kk; sV[wrp] = vv; }
    __syncthreads();
    if (c == 0) {
        float ks = sK[0] + sK[1] + sK[2] + sK[3];
        float vs = sV[0] + sV[1] + sV[2] + sV[3];
        g_kb2[n * 32 + h] = __ldg(kb + h) - ks;
        g_vb2[n * 32 + h] = __ldg(vb + h) - vs;
    }
}

// =====================================================================
// Proj via fp16 mma.sync: D[128s x 64kv], K=128; register softmax partials.
// =====================================================================
__global__ __launch_bounds__(256) void proj_kernel()
{
    extern __shared__ __align__(16) char psm[];
    const uint32_t sbase = smem_u32(psm);
    uint4* sm4 = (uint4*)psm;
    __half* s_invh = (__half*)(psm + 52224);
    float* s_kb = (float*)(psm + 52480);
    float* s_pm = (float*)(psm + 52736);          // [8w][32h]
    float* s_pse = s_pm + 256;
    float* s_psev = s_pse + 256;

    const int n = blockIdx.y, bx = blockIdx.x;
    const int t = threadIdx.x;
    const int w = t >> 5, lane = t & 31;
    const int sub = lane >> 3, i8 = lane & 7;
    const int gid = lane >> 2, tig = lane & 3;

    if (t < 128) s_invh[t] = __float2half(g_inv[n * 128 + t]);
    if (t >= 128 && t < 160) s_kb[t - 128] = g_kb2[n * 32 + (t - 128)];
    if (t >= 160 && t < 192) s_kb[t - 128] = g_vb2[n * 32 + (t - 160)];
    __syncthreads();

    {
        const size_t zb = ((size_t)n * HW + (size_t)bx * 128) * 16;
        for (int e = t; e < 2048; e += 256) {
            int r = e >> 4, u = e & 15;
            uint4 q = g_zh4[zb + e];
            __half2* qq = (__half2*)&q;
            const __half2* iv = (const __half2*)&s_invh[u * 8];
#pragma unroll
            for (int j = 0; j < 4; j++) qq[j] = __hmul2(qq[j], iv[j]);
            sm4[r * 17 + u] = q;
        }
        for (int e = t; e < 1024; e += 256) {
            int r = e >> 4, u = e & 15;
            sm4[2176 + r * 17 + u] = g_wkv4[e];
        }
    }
    __syncthreads();

    const uint32_t AB = sbase;
    const uint32_t WB = sbase + 34816;
    const uint32_t aA = ((i8 + ((sub & 1) << 3)) * 136 + ((sub >> 1) << 3)) * 2;
    const uint32_t aB = ((i8 + ((sub >> 1) << 3)) * 136 + ((sub & 1) << 3)) * 2;

    float acc[4][2][4];
#pragma unroll
    for (int a = 0; a < 4; a++)
#pragma unroll
        for (int b = 0; b < 2; b++)
#pragma unroll
            for (int r = 0; r < 4; r++) acc[a][b][r] = 0.f;

#pragma unroll
    for (int kc = 0; kc < 8; kc++) {
        uint32_t Af[4];
        ldsm4(Af, AB + aA + (uint32_t)((w * 16 * 136 + kc * 16) * 2));
#pragma unroll
        for (int nf2 = 0; nf2 < 4; nf2++) {
            uint32_t Bf[4];
            ldsm4(Bf, WB + aB + (uint32_t)(((nf2 * 16) * 136 + kc * 16) * 2));
            mma16816(acc[nf2][0], Af, Bf);
            mma16816(acc[nf2][1], Af, Bf + 2);
        }
    }

#pragma unroll
    for (int nf2 = 0; nf2 < 4; nf2++) {
#pragma unroll
        for (int half = 0; half < 2; half++) {
            int h = nf2 * 8 + half * 4 + tig;
            float kb2v = s_kb[h], vb2v = s_kb[32 + h];
            float k1 = acc[nf2][half][0] + kb2v;
            float v1 = acc[nf2][half][1] + vb2v;
            float k2 = acc[nf2][half][2] + kb2v;
            float v2 = acc[nf2][half][3] + vb2v;
            float m = fmaxf(k1, k2);
#pragma unroll
            for (int o = 4; o <= 16; o <<= 1)
                m = fmaxf(m, __shfl_xor_sync(0xffffffffu, m, o));
            float e1 = expf(k1 - m), e2 = expf(k2 - m);
            float se = e1 + e2, sev = e1 * v1 + e2 * v2;
#pragma unroll
            for (int o = 4; o <= 16; o <<= 1) {
                se += __shfl_xor_sync(0xffffffffu, se, o);
                sev += __shfl_xor_sync(0xffffffffu, sev, o);
            }
            if (gid == 0) {
                s_pm[w * 32 + h] = m;
                s_pse[w * 32 + h] = se;
                s_psev[w * 32 + h] = sev;
            }
        }
    }
    __syncthreads();

    if (t < 32) {
        int h = t;
        float m = s_pm[h];
#pragma unroll
        for (int ww = 1; ww < 8; ww++) m = fmaxf(m, s_pm[ww * 32 + h]);
        float se = 0.f, sev = 0.f;
#pragma unroll
        for (int ww = 0; ww < 8; ww++) {
            float sc = expf(s_pm[ww * 32 + h] - m);
            se += s_pse[ww * 32 + h] * sc;
            sev += s_psev[ww * 32 + h] * sc;
        }
        int idx = (n * 32 + h) * 512 + bx;
        g_pm[idx] = m;
        g_pse[idx] = se;
        g_psev[idx] = sev;
    }
}

// =====================================================================
// Merge softmax partials (512 per head) -> context[n,h]
// =====================================================================
__global__ void ctx_kernel()
{
    const int nh = blockIdx.x;
    const int t = threadIdx.x;      // 128
    const int base = nh * 512;
    const int lane = t & 31, wrp = t >> 5;
    __shared__ float sred[4];
    __shared__ float sM;

    float lm[4];
    float m = -1e30f;
#pragma unroll
    for (int i = 0; i < 4; i++) {
        lm[i] = g_pm[base + t + 128 * i];
        m = fmaxf(m, lm[i]);
    }
#pragma unroll
    for (int o = 16; o; o >>= 1) m = fmaxf(m, __shfl_xor_sync(0xffffffffu, m, o));
    if (lane == 0) sred[wrp] = m;
    __syncthreads();
    if (t == 0) sM = fmaxf(fmaxf(sred[0], sred[1]), fmaxf(sred[2], sred[3]));
    __syncthreads();
    const float M = sM;

    float S = 0.f, SV = 0.f;
#pragma unroll
    for (int i = 0; i < 4; i++) {
        int idx = base + t + 128 * i;
        float sc = expf(lm[i] - M);
        S += g_pse[idx] * sc;
        SV += g_psev[idx] * sc;
    }
#pragma unroll
    for (int o = 16; o; o >>= 1) {
        S += __shfl_xor_sync(0xffffffffu, S, o);
        SV += __shfl_xor_sync(0xffffffffu, SV, o);
    }
    __shared__ float sS[4], sSV[4];
    if (lane == 0) { sS[wrp] = S; sSV[wrp] = SV; }
    __syncthreads();
    if (t == 0) {
        S = sS[0] + sS[1] + sS[2] + sS[3];
        SV = sSV[0] + sSV[1] + sSV[2] + sSV[3];
        g_ctx[nh] = SV / S;
    }
}

__global__ void biasout_kernel(const float* __restrict__ rw, const float* __restrict__ rb)
{
    int n = blockIdx.x;
    int c = threadIdx.x;   // 128
    float b = __ldg(rb + c);
#pragma unroll
    for (int h = 0; h < 32; h++)
        b += __ldg(rw + c * 32 + h) * g_ctx[n * 32 + h];
    g_bias[n * 128 + c] = b;
}

// =====================================================================
// Out: read fp16 z [s][c], transpose via smem, write NCHW fp32
//      out = z*inv + (bias - mean*inv)
// =====================================================================
__global__ __launch_bounds__(256) void out_kernel(float* __restrict__ out)
{
    extern __shared__ float osm[];          // [128 s][133 c-pad] + inv/off
    float* s_inv = osm + 17024;
    float* s_off = s_inv + 128;

    const int n = blockIdx.y, bx = blockIdx.x;
    const int t = threadIdx.x;
    const int w = t >> 5, lane = t & 31;

    if (t < 128) {
        float iv = g_inv[n * 128 + t];
        s_inv[t] = iv;
        s_off[t] = g_bias[n * 128 + t] - g_mean[n * 128 + t] * iv;
    }

    const size_t zb = ((size_t)n * HW + (size_t)bx * 128) * 16;
    for (int e = t; e < 2048; e += 256) {
        int r = e >> 4, u = e & 15;
        uint4 q = g_zh4[zb + e];
        const __half2* qq = (const __half2*)&q;
        float* d = osm + r * 133 + u * 8;
#pragma unroll
        for (int j = 0; j < 4; j++) {
            float2 f = __half22float2(qq[j]);
            d[2 * j] = f.x; d[2 * j + 1] = f.y;
        }
    }
    __syncthreads();

#pragma unroll
    for (int ci = 0; ci < 16; ci++) {
        int c = w * 16 + ci;
        float iv = s_inv[c], off = s_off[c];
        size_t ob = (size_t)(n * COUT + c) * HW + (size_t)bx * 128;
#pragma unroll
        for (int j = 0; j < 4; j++) {
            int s = lane + 32 * j;
            out[ob + s] = fmaf(osm[s * 133 + c], iv, off);
        }
    }
}

extern "C" void kernel_launch(void* const* d_in, const int* in_sizes, int n_in,
                              void* d_out, int out_size)
{
    const float* x  = (const float*)d_in[0];
    const float* y  = (const float*)d_in[1];
    const float* cw = (const float*)d_in[2];
    const float* cb = (const float*)d_in[3];
    const float* pa = (const float*)d_in[4];
    const float* kw = (const float*)d_in[5];
    const float* kb = (const float*)d_in[6];
    // d_in[7], d_in[8] = queries_w/b: mathematically dead (softmax over size-1 axis)
    const float* vw = (const float*)d_in[9];
    const float* vb = (const float*)d_in[10];
    const float* rw = (const float*)d_in[11];
    const float* rb = (const float*)d_in[12];

    static bool attr_set = false;
    if (!attr_set) {
        cudaFuncSetAttribute(conv_mma_kernel,
                             cudaFuncAttributeMaxDynamicSharedMemorySize, 78112);
        cudaFuncSetAttribute(proj_kernel,
                             cudaFuncAttributeMaxDynamicSharedMemorySize, 56064);
        cudaFuncSetAttribute(out_kernel,
                             cudaFuncAttributeMaxDynamicSharedMemorySize, 69632);
        attr_set = true;
    }

    wprep_kernel<<<144, 256>>>(cw, kw, vw);
    prepass_kernel<<<dim3(2, 256, 8), 256>>>(x, y);
    conv_mma_kernel<<<dim3(2, 256, 8), 256, 78112>>>(cb, pa);
    stats_kernel<<<1024, 256>>>();
    kb2_kernel<<<dim3(32, 8), 128>>>(kw, kb, vw, vb);
    proj_kernel<<<dim3(512, 8), 256, 56064>>>();
    ctx_kernel<<<256, 128>>>();
    biasout_kernel<<<8, 128>>>(rw, rb);
    out_kernel<<<dim3(512, 8), 256, 69632>>>((float*)d_out);
}